// round 9
// baseline (speedup 1.0000x reference)
#include <cuda_runtime.h>
#include <cuda_bf16.h>
#include <cstdint>

#define B_ 1024
#define T_ 200
#define D_ 128
#define U_ 128
#define G_ 384   // 3*U

typedef unsigned long long ull;

// Scratch (no cudaMalloc allowed)
__device__ float g_xm[(size_t)B_ * T_ * G_];
__device__ int   g_perm[B_];
__device__ __nv_bfloat16 g_whi[G_ * D_];   // [g][k] transposed hi(W)
__device__ __nv_bfloat16 g_wlo[G_ * D_];   // [g][k] transposed lo(W)

// ---------- f32x2 helpers ----------
__device__ __forceinline__ ull pack_dup(float x) {
    ull r; asm("mov.b64 %0, {%1, %1};" : "=l"(r) : "f"(x)); return r;
}
__device__ __forceinline__ ull pack2(float x, float y) {
    ull r; asm("mov.b64 %0, {%1, %2};" : "=l"(r) : "f"(x), "f"(y)); return r;
}
__device__ __forceinline__ void ffma2(ull& d, ull a, ull b) {
    asm("fma.rn.f32x2 %0, %1, %2, %0;" : "+l"(d) : "l"(a), "l"(b));
}
__device__ __forceinline__ ull addf2(ull a, ull b) {
    ull r; asm("add.rn.f32x2 %0, %1, %2;" : "=l"(r) : "l"(a), "l"(b)); return r;
}
__device__ __forceinline__ float2 unpack2(ull v) {
    float2 f; asm("mov.b64 {%0, %1}, %2;" : "=f"(f.x), "=f"(f.y) : "l"(v)); return f;
}
__device__ __forceinline__ float sigm(float x) {
    return __fdividef(1.0f, 1.0f + __expf(-x));
}
__device__ __forceinline__ float tanh_fast(float x) {
    return 1.0f - __fdividef(2.0f, __expf(2.0f * x) + 1.0f);
}

// ---------- tensor helpers ----------
__device__ __forceinline__ void ldsm4(uint32_t& r0, uint32_t& r1, uint32_t& r2, uint32_t& r3, uint32_t addr) {
    asm volatile("ldmatrix.sync.aligned.m8n8.x4.shared.b16 {%0,%1,%2,%3}, [%4];"
                 : "=r"(r0), "=r"(r1), "=r"(r2), "=r"(r3) : "r"(addr));
}
__device__ __forceinline__ void mma16816(float* d, uint32_t a0, uint32_t a1, uint32_t a2, uint32_t a3,
                                         uint32_t b0, uint32_t b1) {
    asm volatile("mma.sync.aligned.m16n8k16.row.col.f32.bf16.bf16.f32 "
                 "{%0,%1,%2,%3},{%4,%5,%6,%7},{%8,%9},{%0,%1,%2,%3};"
                 : "+f"(d[0]), "+f"(d[1]), "+f"(d[2]), "+f"(d[3])
                 : "r"(a0), "r"(a1), "r"(a2), "r"(a3), "r"(b0), "r"(b1));
}
__device__ __forceinline__ uint32_t pack_bf2(__nv_bfloat16 a, __nv_bfloat16 b) {
    uint16_t ua = *(uint16_t*)&a, ub = *(uint16_t*)&b;
    return (uint32_t)ua | ((uint32_t)ub << 16);
}

// ---------- Kernel 0: bitonic sort of batch rows by length (ascending) ----------
__global__ void sort_rows_kernel(const int* __restrict__ slen) {
    __shared__ int key[B_];
    int tid = threadIdx.x;
    key[tid] = slen[tid] * 1024 + tid;
    __syncthreads();
    for (int size = 2; size <= B_; size <<= 1) {
        for (int stride = size >> 1; stride > 0; stride >>= 1) {
            int j = tid ^ stride;
            if (j > tid) {
                int a = key[tid], b = key[j];
                bool up = (tid & size) == 0;
                if ((a > b) == up) { key[tid] = b; key[j] = a; }
            }
            __syncthreads();
        }
    }
    g_perm[tid] = key[tid] & (B_ - 1);
}

// ---------- Kernel 0b: split W into transposed bf16 hi/lo ----------
__global__ void wsplit_kernel(const float* __restrict__ W) {
    int idx = blockIdx.x * 256 + threadIdx.x;   // 49152 = 128*384
    int k = idx / G_, g = idx - k * G_;
    float w = W[(size_t)k * G_ + g];
    __nv_bfloat16 hi = __float2bfloat16(w);
    __nv_bfloat16 lo = __float2bfloat16(w - __bfloat162float(hi));
    g_whi[g * D_ + k] = hi;
    g_wlo[g * D_ + k] = lo;
}

// ---------- Kernel 1: input GEMM via bf16-split-3 tensor cores ----------
__global__ __launch_bounds__(256, 2) void gemm_in_kernel(
    const float* __restrict__ X, const int* __restrict__ slen,
    const float* __restrict__ bias)
{
    int b  = blockIdx.z;
    int t0 = blockIdx.y * 64;
    int n0 = blockIdx.x * 128;
    if (t0 >= slen[b]) return;

    extern __shared__ char smem[];
    __nv_bfloat16* Xhi = (__nv_bfloat16*)smem;   // [64][128]
    __nv_bfloat16* Xlo = Xhi + 64 * 128;         // [64][128]
    __nv_bfloat16* Whi = Xlo + 64 * 128;         // [128][128]
    __nv_bfloat16* Wlo = Whi + 128 * 128;        // [128][128]
    int tid = threadIdx.x;

    const float4* Xg = (const float4*)(X + (size_t)b * T_ * D_);
#pragma unroll
    for (int i = 0; i < 8; i++) {
        int idx = i * 256 + tid;
        int row = idx >> 5, dq = idx & 31;
        int t = t0 + row;
        float4 v = make_float4(0.f, 0.f, 0.f, 0.f);
        if (t < T_) v = Xg[t * 32 + dq];
        __nv_bfloat16 hx = __float2bfloat16(v.x), hy = __float2bfloat16(v.y);
        __nv_bfloat16 hz = __float2bfloat16(v.z), hw = __float2bfloat16(v.w);
        __nv_bfloat16 lx = __float2bfloat16(v.x - __bfloat162float(hx));
        __nv_bfloat16 ly = __float2bfloat16(v.y - __bfloat162float(hy));
        __nv_bfloat16 lz = __float2bfloat16(v.z - __bfloat162float(hz));
        __nv_bfloat16 lw = __float2bfloat16(v.w - __bfloat162float(hw));
        int off = row * 128 + (((dq >> 1) ^ (row & 7)) << 3) + (dq & 1) * 4;
        uint2 hv; hv.x = pack_bf2(hx, hy); hv.y = pack_bf2(hz, hw);
        uint2 lv; lv.x = pack_bf2(lx, ly); lv.y = pack_bf2(lz, lw);
        *(uint2*)(Xhi + off) = hv;
        *(uint2*)(Xlo + off) = lv;
    }
    const uint4* WhiG = (const uint4*)g_whi;
    const uint4* WloG = (const uint4*)g_wlo;
#pragma unroll
    for (int i = 0; i < 8; i++) {
        int idx = i * 256 + tid;
        int n = idx >> 4, c8 = idx & 15;
        int src = (n0 + n) * 16 + c8;
        int dst = n * 16 + (c8 ^ (n & 7));
        ((uint4*)Whi)[dst] = WhiG[src];
        ((uint4*)Wlo)[dst] = WloG[src];
    }
    __syncthreads();

    int lane = tid & 31, wid = tid >> 5;
    int m_off = (wid & 3) * 16;
    int n_off = (wid >> 2) * 64;

    uint32_t XhiB = (uint32_t)__cvta_generic_to_shared(Xhi);
    uint32_t XloB = (uint32_t)__cvta_generic_to_shared(Xlo);
    uint32_t WhiB = (uint32_t)__cvta_generic_to_shared(Whi);
    uint32_t WloB = (uint32_t)__cvta_generic_to_shared(Wlo);

    int ar = m_off + (lane & 15);
    uint32_t arow = ar * 256, axor = (ar & 7), ahi = lane >> 4;
    int brn = n_off + ((lane >> 4) << 3) + (lane & 7);
    uint32_t brow0 = brn * 256, bxor = (brn & 7), bhi = (lane >> 3) & 1;

    float d[8][4];
#pragma unroll
    for (int f = 0; f < 8; f++)
#pragma unroll
        for (int r = 0; r < 4; r++) d[f][r] = 0.f;

#pragma unroll
    for (int ch = 0; ch < 3; ch++) {
        uint32_t Ab = (ch < 2) ? XhiB : XloB;
        uint32_t Bb = (ch == 1) ? WloB : WhiB;
#pragma unroll
        for (int ks = 0; ks < 8; ks++) {
            uint32_t c = ks * 2;
            uint32_t a0, a1, a2, a3;
            ldsm4(a0, a1, a2, a3, Ab + arow + (((c + ahi) ^ axor) << 4));
#pragma unroll
            for (int nb = 0; nb < 4; nb++) {
                uint32_t b0, b1, b2, b3;
                ldsm4(b0, b1, b2, b3, Bb + brow0 + nb * 16 * 256 + (((c + bhi) ^ bxor) << 4));
                mma16816(d[2 * nb],     a0, a1, a2, a3, b0, b1);
                mma16816(d[2 * nb + 1], a0, a1, a2, a3, b2, b3);
            }
        }
    }

    int rloc = m_off + (lane >> 2);
    int trow0 = t0 + rloc, trow1 = trow0 + 8;
    float* o0 = g_xm + ((size_t)b * T_ + trow0) * G_ + n0;
    float* o1 = g_xm + ((size_t)b * T_ + trow1) * G_ + n0;
#pragma unroll
    for (int f = 0; f < 8; f++) {
        int col = n_off + (f >> 1) * 16 + (f & 1) * 8 + (lane & 3) * 2;
        float2 bv = *(const float2*)(bias + n0 + col);
        if (trow0 < T_) *(float2*)(o0 + col) = make_float2(d[f][0] + bv.x, d[f][1] + bv.y);
        if (trow1 < T_) *(float2*)(o1 + col) = make_float2(d[f][2] + bv.x, d[f][3] + bv.y);
    }
}

// ---------- Kernel 2: recurrence, 4-way split-k, 512 threads ----------
// 128 blocks x 512 threads (16 warps = 4/SMSP for latency hiding), 2-pass pairing.
// Group g = tid>>7 (128 threads each): kk in [g*16, g*16+16); owns gates of row g.
// Join via psum[4][128][6]; gate phase fully parallel across 512 threads.
__global__ __launch_bounds__(512, 1) void recur_kernel(
    const int* __restrict__ slen, const float* __restrict__ R,
    const float* __restrict__ bias, float* __restrict__ out)
{
    extern __shared__ char smraw[];
    ull*    Rzr2 = (ull*)smraw;                                  // [64kk][128u][2]  131072
    float2* Rh2  = (float2*)(smraw + 131072);                    // [64kk][128u]      65536
    ull*    hd   = (ull*)(smraw + 131072 + 65536);               // [128k][4] dup      4096
    ull*    hp   = (ull*)(smraw + 131072 + 65536 + 4096);        // [128k][2] pairs    2048
    ull*    psum = (ull*)(smraw + 131072 + 65536 + 4096 + 2048); // [4][128][6]       24576
    __shared__ int rows_s[4], len_s[4];

    int tid = threadIdx.x;
    int u   = tid & 127;
    int g   = tid >> 7;        // 0..3

    // R fill: packed layout, 24 independent LDG.128/thread
    {
        const float4* R4 = (const float4*)R;
#pragma unroll 8
        for (int i = 0; i < 24; i++) {
            int f = i * 512 + tid;
            float4 v = R4[f];
            int k = f / 96;
            int c = (f - k * 96) * 4;
            int kk = k >> 1, kp = k & 1;
            if (c < 128) {
                float* dst = (float*)&Rzr2[(kk * 128 + c) * 2 + kp];
                dst[0] = v.x; dst[4] = v.y; dst[8] = v.z; dst[12] = v.w;
            } else if (c < 256) {
                float* dst = (float*)&Rzr2[(kk * 128 + (c - 128)) * 2 + kp] + 1;
                dst[0] = v.x; dst[4] = v.y; dst[8] = v.z; dst[12] = v.w;
            } else {
                float* dst = (float*)&Rh2[kk * 128 + (c - 256)] + kp;
                dst[0] = v.x; dst[2] = v.y; dst[4] = v.z; dst[6] = v.w;
            }
        }
    }

    ull brzr = pack2(bias[G_ + u], bias[G_ + u + 128]);
    ull brh  = pack_dup(bias[G_ + u + 256]);

    int kk0 = g * 16;
    int slot_h = (g < 2) ? 4 : 5;

    for (int pass = 0; pass < 2; pass++) {
        int gidx = (pass == 0) ? (int)blockIdx.x : (255 - (int)blockIdx.x);

        if (tid < 4) {
            int idx = B_ - 1 - (gidx * 4 + tid);
            int row = g_perm[idx];
            rows_s[tid] = row;
            len_s[tid]  = slen[row];
        }
        if (tid < 128 * 4) hd[tid] = 0ULL;
        if (tid < 128 * 2) hp[tid] = 0ULL;
        __syncthreads();

        int maxlen = max(max(len_s[0], len_s[1]), max(len_s[2], len_s[3]));
        int leng = len_s[g];

        const float* xbg = g_xm + (size_t)rows_s[g] * T_ * G_ + u;
        float*       obg = out + (size_t)rows_s[g] * T_ * U_ + u;

        float hg = 0.f, pog = 0.f;

        const ull*    Rp  = Rzr2 + u * 2;
        const float2* Rhp = Rh2 + u;

        for (int t = 0; t < maxlen; t++) {
            // prefetch this row's xm (3 LDGs, hidden behind matmul)
            size_t toff = (size_t)t * G_;
            float xz = xbg[toff], xr = xbg[toff + 128], xh = xbg[toff + 256];

            ull az0, az1, az2, az3, ah01, ah23;
            if (g == 0) { az0 = az1 = az2 = az3 = brzr; ah01 = ah23 = brh; }
            else        { az0 = az1 = az2 = az3 = 0ULL; ah01 = ah23 = 0ULL; }

#pragma unroll 4
            for (int kk = kk0; kk < kk0 + 16; kk++) {
                ulonglong2 rzr2 = *(const ulonglong2*)(Rp + kk * 256);
                float2 rh2v = Rhp[kk * 128];
                const ull* hck = hd + kk * 8;
                ulonglong2 hA0 = *(const ulonglong2*)(hck);       // k=2kk rows 0,1 dup
                ulonglong2 hB0 = *(const ulonglong2*)(hck + 2);   // k=2kk rows 2,3 dup
                ulonglong2 hA1 = *(const ulonglong2*)(hck + 4);   // k=2kk+1
                ulonglong2 hB1 = *(const ulonglong2*)(hck + 6);
                const ull* hpk = hp + kk * 4;
                ulonglong2 hp0 = *(const ulonglong2*)(hpk);       // (h0,h1),(h2,h3) @k=2kk
                ulonglong2 hp1 = *(const ulonglong2*)(hpk + 2);   // @k=2kk+1
                ull rh0 = pack_dup(rh2v.x);
                ull rh1 = pack_dup(rh2v.y);
                ffma2(az0, hA0.x, rzr2.x); ffma2(az1, hA0.y, rzr2.x);
                ffma2(az2, hB0.x, rzr2.x); ffma2(az3, hB0.y, rzr2.x);
                ffma2(ah01, hp0.x, rh0);   ffma2(ah23, hp0.y, rh0);
                ffma2(az0, hA1.x, rzr2.y); ffma2(az1, hA1.y, rzr2.y);
                ffma2(az2, hB1.x, rzr2.y); ffma2(az3, hB1.y, rzr2.y);
                ffma2(ah01, hp1.x, rh1);   ffma2(ah23, hp1.y, rh1);
            }

            // post partials for other groups (skip own row's az)
            {
                ull* ps = psum + ((g << 7) + u) * 6;
                if (g != 0) ps[0] = az0;
                if (g != 1) ps[1] = az1;
                if (g != 2) ps[2] = az2;
                if (g != 3) ps[3] = az3;
                ps[4] = ah01;
                ps[5] = ah23;
            }
            __syncthreads();   // bar1: partials ready; all h reads done

            {
                ull e  = (g == 0) ? az0 : (g == 1) ? az1 : (g == 2) ? az2 : az3;
                ull eh = (g < 2) ? ah01 : ah23;
#pragma unroll
                for (int s = 0; s < 4; s++) {
                    if (s == g) continue;
                    const ull* ps = psum + ((s << 7) + u) * 6;
                    e  = addf2(e,  ps[g]);
                    eh = addf2(eh, ps[slot_h]);
                }
                float2 a   = unpack2(e);
                float2 ahv = unpack2(eh);
                float ih = (g & 1) ? ahv.y : ahv.x;
                float z = sigm(xz + a.x), r = sigm(xr + a.y);
                float hh = tanh_fast(xh + r * ih);
                float v = z * hg + (1.0f - z) * hh;
                bool m = t < leng;
                hg = m ? v : hg; pog = m ? v : pog;
                obg[(size_t)t * U_] = pog;
                // publish h for row g: dup + pair lanes
                hd[u * 4 + g] = pack_dup(hg);
                ((float*)hp)[u * 4 + g] = hg;
            }
            __syncthreads();   // bar2: new h published
        }

        // tail: frozen outputs (each group stores its row)
        for (int t = maxlen; t < T_; t++) {
            obg[(size_t)t * U_] = pog;
        }
        __syncthreads();
    }
}

extern "C" void kernel_launch(void* const* d_in, const int* in_sizes, int n_in,
                              void* d_out, int out_size)
{
    const float* X    = (const float*)d_in[0];   // [B][T][D]
    const int*   slen = (const int*)d_in[1];     // [B][1]
    const float* W    = (const float*)d_in[2];   // [D][3U]
    const float* R    = (const float*)d_in[3];   // [U][3U]
    const float* bias = (const float*)d_in[4];   // [2][3U]
    float* out = (float*)d_out;                  // [B][T][U]

    (void)in_sizes; (void)n_in; (void)out_size;

    const int gemm_smem  = (64 * 128 * 2 + 128 * 128 * 2) * 2;            // 98304 B
    const int recur_smem = 131072 + 65536 + 4096 + 2048 + 24576;          // 227328 B

    cudaFuncSetAttribute(gemm_in_kernel, cudaFuncAttributeMaxDynamicSharedMemorySize, gemm_smem);
    cudaFuncSetAttribute(recur_kernel,  cudaFuncAttributeMaxDynamicSharedMemorySize, recur_smem);

    sort_rows_kernel<<<1, B_>>>(slen);
    wsplit_kernel<<<192, 256>>>(W);

    dim3 ggrid(3, 4, B_);
    gemm_in_kernel<<<ggrid, 256, gemm_smem>>>(X, slen, bias);

    recur_kernel<<<128, 512, recur_smem>>>(slen, R, bias, out);
}

// round 10
// speedup vs baseline: 1.3367x; 1.3367x over previous
#include <cuda_runtime.h>
#include <cuda_bf16.h>
#include <cstdint>

#define B_ 1024
#define T_ 200
#define D_ 128
#define U_ 128
#define G_ 384   // 3*U

typedef unsigned long long ull;

// Scratch (no cudaMalloc allowed)
__device__ float g_xm[(size_t)B_ * T_ * G_];
__device__ int   g_perm[B_];
__device__ __nv_bfloat16 g_whi[G_ * D_];   // [g][k] transposed hi(W)
__device__ __nv_bfloat16 g_wlo[G_ * D_];   // [g][k] transposed lo(W)

// ---------- f32x2 helpers ----------
__device__ __forceinline__ ull pack_dup(float x) {
    ull r; asm("mov.b64 %0, {%1, %1};" : "=l"(r) : "f"(x)); return r;
}
__device__ __forceinline__ ull pack2(float x, float y) {
    ull r; asm("mov.b64 %0, {%1, %2};" : "=l"(r) : "f"(x), "f"(y)); return r;
}
__device__ __forceinline__ void ffma2(ull& d, ull a, ull b) {
    asm("fma.rn.f32x2 %0, %1, %2, %0;" : "+l"(d) : "l"(a), "l"(b));
}
__device__ __forceinline__ ull addf2(ull a, ull b) {
    ull r; asm("add.rn.f32x2 %0, %1, %2;" : "=l"(r) : "l"(a), "l"(b)); return r;
}
__device__ __forceinline__ float2 unpack2(ull v) {
    float2 f; asm("mov.b64 {%0, %1}, %2;" : "=f"(f.x), "=f"(f.y) : "l"(v)); return f;
}
__device__ __forceinline__ float sigm(float x) {
    return __fdividef(1.0f, 1.0f + __expf(-x));
}
__device__ __forceinline__ float tanh_fast(float x) {
    return 1.0f - __fdividef(2.0f, __expf(2.0f * x) + 1.0f);
}

// ---------- tensor helpers ----------
__device__ __forceinline__ void ldsm4(uint32_t& r0, uint32_t& r1, uint32_t& r2, uint32_t& r3, uint32_t addr) {
    asm volatile("ldmatrix.sync.aligned.m8n8.x4.shared.b16 {%0,%1,%2,%3}, [%4];"
                 : "=r"(r0), "=r"(r1), "=r"(r2), "=r"(r3) : "r"(addr));
}
__device__ __forceinline__ void mma16816(float* d, uint32_t a0, uint32_t a1, uint32_t a2, uint32_t a3,
                                         uint32_t b0, uint32_t b1) {
    asm volatile("mma.sync.aligned.m16n8k16.row.col.f32.bf16.bf16.f32 "
                 "{%0,%1,%2,%3},{%4,%5,%6,%7},{%8,%9},{%0,%1,%2,%3};"
                 : "+f"(d[0]), "+f"(d[1]), "+f"(d[2]), "+f"(d[3])
                 : "r"(a0), "r"(a1), "r"(a2), "r"(a3), "r"(b0), "r"(b1));
}
__device__ __forceinline__ uint32_t pack_bf2(__nv_bfloat16 a, __nv_bfloat16 b) {
    uint16_t ua = *(uint16_t*)&a, ub = *(uint16_t*)&b;
    return (uint32_t)ua | ((uint32_t)ub << 16);
}

// ---------- Kernel 0: bitonic sort of batch rows by length (ascending) ----------
__global__ void sort_rows_kernel(const int* __restrict__ slen) {
    __shared__ int key[B_];
    int tid = threadIdx.x;
    key[tid] = slen[tid] * 1024 + tid;
    __syncthreads();
    for (int size = 2; size <= B_; size <<= 1) {
        for (int stride = size >> 1; stride > 0; stride >>= 1) {
            int j = tid ^ stride;
            if (j > tid) {
                int a = key[tid], b = key[j];
                bool up = (tid & size) == 0;
                if ((a > b) == up) { key[tid] = b; key[j] = a; }
            }
            __syncthreads();
        }
    }
    g_perm[tid] = key[tid] & (B_ - 1);
}

// ---------- Kernel 0b: split W into transposed bf16 hi/lo ----------
__global__ void wsplit_kernel(const float* __restrict__ W) {
    int idx = blockIdx.x * 256 + threadIdx.x;   // 49152 = 128*384
    int k = idx / G_, g = idx - k * G_;
    float w = W[(size_t)k * G_ + g];
    __nv_bfloat16 hi = __float2bfloat16(w);
    __nv_bfloat16 lo = __float2bfloat16(w - __bfloat162float(hi));
    g_whi[g * D_ + k] = hi;
    g_wlo[g * D_ + k] = lo;
}

// ---------- Kernel 1: input GEMM via bf16-split-3 tensor cores (unchanged) ----------
__global__ __launch_bounds__(256, 2) void gemm_in_kernel(
    const float* __restrict__ X, const int* __restrict__ slen,
    const float* __restrict__ bias)
{
    int b  = blockIdx.z;
    int t0 = blockIdx.y * 64;
    int n0 = blockIdx.x * 128;
    if (t0 >= slen[b]) return;

    extern __shared__ char smem[];
    __nv_bfloat16* Xhi = (__nv_bfloat16*)smem;   // [64][128]
    __nv_bfloat16* Xlo = Xhi + 64 * 128;         // [64][128]
    __nv_bfloat16* Whi = Xlo + 64 * 128;         // [128][128]
    __nv_bfloat16* Wlo = Whi + 128 * 128;        // [128][128]
    int tid = threadIdx.x;

    const float4* Xg = (const float4*)(X + (size_t)b * T_ * D_);
#pragma unroll
    for (int i = 0; i < 8; i++) {
        int idx = i * 256 + tid;
        int row = idx >> 5, dq = idx & 31;
        int t = t0 + row;
        float4 v = make_float4(0.f, 0.f, 0.f, 0.f);
        if (t < T_) v = Xg[t * 32 + dq];
        __nv_bfloat16 hx = __float2bfloat16(v.x), hy = __float2bfloat16(v.y);
        __nv_bfloat16 hz = __float2bfloat16(v.z), hw = __float2bfloat16(v.w);
        __nv_bfloat16 lx = __float2bfloat16(v.x - __bfloat162float(hx));
        __nv_bfloat16 ly = __float2bfloat16(v.y - __bfloat162float(hy));
        __nv_bfloat16 lz = __float2bfloat16(v.z - __bfloat162float(hz));
        __nv_bfloat16 lw = __float2bfloat16(v.w - __bfloat162float(hw));
        int off = row * 128 + (((dq >> 1) ^ (row & 7)) << 3) + (dq & 1) * 4;
        uint2 hv; hv.x = pack_bf2(hx, hy); hv.y = pack_bf2(hz, hw);
        uint2 lv; lv.x = pack_bf2(lx, ly); lv.y = pack_bf2(lz, lw);
        *(uint2*)(Xhi + off) = hv;
        *(uint2*)(Xlo + off) = lv;
    }
    const uint4* WhiG = (const uint4*)g_whi;
    const uint4* WloG = (const uint4*)g_wlo;
#pragma unroll
    for (int i = 0; i < 8; i++) {
        int idx = i * 256 + tid;
        int n = idx >> 4, c8 = idx & 15;
        int src = (n0 + n) * 16 + c8;
        int dst = n * 16 + (c8 ^ (n & 7));
        ((uint4*)Whi)[dst] = WhiG[src];
        ((uint4*)Wlo)[dst] = WloG[src];
    }
    __syncthreads();

    int lane = tid & 31, wid = tid >> 5;
    int m_off = (wid & 3) * 16;
    int n_off = (wid >> 2) * 64;

    uint32_t XhiB = (uint32_t)__cvta_generic_to_shared(Xhi);
    uint32_t XloB = (uint32_t)__cvta_generic_to_shared(Xlo);
    uint32_t WhiB = (uint32_t)__cvta_generic_to_shared(Whi);
    uint32_t WloB = (uint32_t)__cvta_generic_to_shared(Wlo);

    int ar = m_off + (lane & 15);
    uint32_t arow = ar * 256, axor = (ar & 7), ahi = lane >> 4;
    int brn = n_off + ((lane >> 4) << 3) + (lane & 7);
    uint32_t brow0 = brn * 256, bxor = (brn & 7), bhi = (lane >> 3) & 1;

    float d[8][4];
#pragma unroll
    for (int f = 0; f < 8; f++)
#pragma unroll
        for (int r = 0; r < 4; r++) d[f][r] = 0.f;

#pragma unroll
    for (int ch = 0; ch < 3; ch++) {
        uint32_t Ab = (ch < 2) ? XhiB : XloB;
        uint32_t Bb = (ch == 1) ? WloB : WhiB;
#pragma unroll
        for (int ks = 0; ks < 8; ks++) {
            uint32_t c = ks * 2;
            uint32_t a0, a1, a2, a3;
            ldsm4(a0, a1, a2, a3, Ab + arow + (((c + ahi) ^ axor) << 4));
#pragma unroll
            for (int nb = 0; nb < 4; nb++) {
                uint32_t b0, b1, b2, b3;
                ldsm4(b0, b1, b2, b3, Bb + brow0 + nb * 16 * 256 + (((c + bhi) ^ bxor) << 4));
                mma16816(d[2 * nb],     a0, a1, a2, a3, b0, b1);
                mma16816(d[2 * nb + 1], a0, a1, a2, a3, b2, b3);
            }
        }
    }

    int rloc = m_off + (lane >> 2);
    int trow0 = t0 + rloc, trow1 = trow0 + 8;
    float* o0 = g_xm + ((size_t)b * T_ + trow0) * G_ + n0;
    float* o1 = g_xm + ((size_t)b * T_ + trow1) * G_ + n0;
#pragma unroll
    for (int f = 0; f < 8; f++) {
        int col = n_off + (f >> 1) * 16 + (f & 1) * 8 + (lane & 3) * 2;
        float2 bv = *(const float2*)(bias + n0 + col);
        if (trow0 < T_) *(float2*)(o0 + col) = make_float2(d[f][0] + bv.x, d[f][1] + bv.y);
        if (trow1 < T_) *(float2*)(o1 + col) = make_float2(d[f][2] + bv.x, d[f][3] + bv.y);
    }
}

// ---------- Kernel 2: recurrence, row-paired accumulation, 256 threads ----------
// 128 blocks x 256 threads, 2-pass pairing (group b then 255-b).
// Group g = tid>>7 covers k in [64g, 64g+64) and owns gates of rows {2g, 2g+1}.
// Accumulators row-paired: z01=(rows0,1), z23, r01, r23, g01, g23.
// h kept ONLY as hp[k] = (h0,h1,h2,h3): one 16B broadcast per k per warp.
// R in 3 plain fp32 arrays; dup movs on R scalars (ALU, non-binding).
__global__ __launch_bounds__(256, 1) void recur_kernel(
    const int* __restrict__ slen, const float* __restrict__ R,
    const float* __restrict__ bias, float* __restrict__ out)
{
    extern __shared__ char smraw[];
    float* Rzs = (float*)smraw;                   // [128k][128u]  65536
    float* Rrs = Rzs + 128 * 128;                 // [128k][128u]  65536
    float* Rhs = Rrs + 128 * 128;                 // [128k][128u]  65536
    float* hpb = Rhs + 128 * 128;                 // [2][128k][4]   4096
    ull*   psum = (ull*)(hpb + 2 * 128 * 4);      // [2][128u][3]   6144
    __shared__ int rows_s[4], len_s[4];

    int tid = threadIdx.x;
    int u   = tid & 127;
    int g   = tid >> 7;        // 0 or 1

    // ---- R fill: 48 independent LDG.128/thread; float4 never straddles a gate ----
    {
        const float4* R4 = (const float4*)R;   // 12288 float4s
#pragma unroll 8
        for (int i = 0; i < 48; i++) {
            int f = i * 256 + tid;
            float4 v = R4[f];
            int k = f / 96;
            int c = (f - k * 96) * 4;          // 0..380, multiple of 4
            float* dst;
            if (c < 128)       dst = Rzs + k * 128 + c;
            else if (c < 256)  dst = Rrs + k * 128 + (c - 128);
            else               dst = Rhs + k * 128 + (c - 256);
            *(float4*)dst = v;
        }
    }

    ull bz2 = pack_dup(bias[G_ + u]);
    ull br2 = pack_dup(bias[G_ + u + 128]);
    ull bh2 = pack_dup(bias[G_ + u + 256]);

    int k0 = g * 64;

    for (int pass = 0; pass < 2; pass++) {
        int gidx = (pass == 0) ? (int)blockIdx.x : (255 - (int)blockIdx.x);

        if (tid < 4) {
            int idx = B_ - 1 - (gidx * 4 + tid);   // descending lengths
            int row = g_perm[idx];
            rows_s[tid] = row;
            len_s[tid]  = slen[row];
        }
        // zero both hp buffers (1024 floats)
#pragma unroll
        for (int i = 0; i < 4; i++) hpb[i * 256 + tid] = 0.0f;
        __syncthreads();

        int maxlen = max(max(len_s[0], len_s[1]), max(len_s[2], len_s[3]));
        int rP = 2 * g, rQ = 2 * g + 1;
        int lenP = len_s[rP], lenQ = len_s[rQ];

        const float* xbP = g_xm + (size_t)rows_s[rP] * T_ * G_ + u;
        const float* xbQ = g_xm + (size_t)rows_s[rQ] * T_ * G_ + u;
        float* obP = out + (size_t)rows_s[rP] * T_ * U_ + u;
        float* obQ = out + (size_t)rows_s[rQ] * T_ * U_ + u;

        float hPv = 0.f, hQv = 0.f, poP = 0.f, poQ = 0.f;

        const float* RzU = Rzs + u;
        const float* RrU = Rrs + u;
        const float* RhU = Rhs + u;

        for (int t = 0; t < maxlen; t++) {
            // prefetch this thread's 2 rows of xm (6 LDG, hidden behind matvec)
            size_t toff = (size_t)t * G_;
            float xzP = xbP[toff], xrP = xbP[toff + 128], xhP = xbP[toff + 256];
            float xzQ = xbQ[toff], xrQ = xbQ[toff + 128], xhQ = xbQ[toff + 256];

            const float* hpc = hpb + (t & 1) * 512;
            // row-paired accumulators; bias only in group 0
            ull z01, z23, r01, r23, q01, q23;
            if (g == 0) { z01 = z23 = bz2; r01 = r23 = br2; q01 = q23 = bh2; }
            else        { z01 = z23 = 0ULL; r01 = r23 = 0ULL; q01 = q23 = 0ULL; }

#pragma unroll 4
            for (int k = k0; k < k0 + 64; k++) {
                float rzv = RzU[k * 128];
                float rrv = RrU[k * 128];
                float rhv = RhU[k * 128];
                ulonglong2 hv = *(const ulonglong2*)(hpc + k * 4);  // (h0,h1),(h2,h3)
                ull rz2 = pack_dup(rzv);
                ull rr2 = pack_dup(rrv);
                ull rh2 = pack_dup(rhv);
                ffma2(z01, hv.x, rz2); ffma2(z23, hv.y, rz2);
                ffma2(r01, hv.x, rr2); ffma2(r23, hv.y, rr2);
                ffma2(q01, hv.x, rh2); ffma2(q23, hv.y, rh2);
            }

            // post the pair the OTHER group needs
            {
                ull* ps = psum + ((size_t)g * 128 + u) * 3;
                if (g == 0) { ps[0] = z23; ps[1] = r23; ps[2] = q23; }
                else        { ps[0] = z01; ps[1] = r01; ps[2] = q01; }
            }
            __syncthreads();   // bar1: partials posted; all hp reads done

            {
                const ull* po = psum + ((size_t)(1 - g) * 128 + u) * 3;
                ull ez = addf2((g == 0) ? z01 : z23, po[0]);
                ull er = addf2((g == 0) ? r01 : r23, po[1]);
                ull eq = addf2((g == 0) ? q01 : q23, po[2]);
                float2 az = unpack2(ez), arv = unpack2(er), aq = unpack2(eq);

                // row P = 2g
                {
                    float z = sigm(xzP + az.x), r = sigm(xrP + arv.x);
                    float hh = tanh_fast(xhP + r * aq.x);
                    float v = z * hPv + (1.0f - z) * hh;
                    bool m = t < lenP;
                    hPv = m ? v : hPv; poP = m ? v : poP;
                    obP[(size_t)t * U_] = poP;
                }
                // row Q = 2g+1
                {
                    float z = sigm(xzQ + az.y), r = sigm(xrQ + arv.y);
                    float hh = tanh_fast(xhQ + r * aq.y);
                    float v = z * hQv + (1.0f - z) * hh;
                    bool m = t < lenQ;
                    hQv = m ? v : hQv; poQ = m ? v : poQ;
                    obQ[(size_t)t * U_] = poQ;
                }
                // publish this thread's 2 h values into the next hp buffer
                float* hn = hpb + ((t + 1) & 1) * 512;
                *(ull*)(hn + u * 4 + 2 * g) = pack2(hPv, hQv);
            }
            __syncthreads();   // bar2: new hp published
        }

        // tail: frozen outputs
        for (int t = maxlen; t < T_; t++) {
            obP[(size_t)t * U_] = poP;
            obQ[(size_t)t * U_] = poQ;
        }
        __syncthreads();   // protect rows_s/len_s + hp before next pass
    }
}

extern "C" void kernel_launch(void* const* d_in, const int* in_sizes, int n_in,
                              void* d_out, int out_size)
{
    const float* X    = (const float*)d_in[0];   // [B][T][D]
    const int*   slen = (const int*)d_in[1];     // [B][1]
    const float* W    = (const float*)d_in[2];   // [D][3U]
    const float* R    = (const float*)d_in[3];   // [U][3U]
    const float* bias = (const float*)d_in[4];   // [2][3U]
    float* out = (float*)d_out;                  // [B][T][U]

    (void)in_sizes; (void)n_in; (void)out_size;

    const int gemm_smem  = (64 * 128 * 2 + 128 * 128 * 2) * 2;    // 98304 B
    const int recur_smem = 3 * 128 * 128 * 4 + 4096 + 6144;       // 206848 B

    cudaFuncSetAttribute(gemm_in_kernel, cudaFuncAttributeMaxDynamicSharedMemorySize, gemm_smem);
    cudaFuncSetAttribute(recur_kernel,  cudaFuncAttributeMaxDynamicSharedMemorySize, recur_smem);

    sort_rows_kernel<<<1, B_>>>(slen);
    wsplit_kernel<<<192, 256>>>(W);

    dim3 ggrid(3, 4, B_);
    gemm_in_kernel<<<ggrid, 256, gemm_smem>>>(X, slen, bias);

    recur_kernel<<<128, 256, recur_smem>>>(slen, R, bias, out);
}

// round 11
// speedup vs baseline: 1.5469x; 1.1573x over previous
#include <cuda_runtime.h>
#include <cuda_bf16.h>
#include <cstdint>

#define B_ 1024
#define T_ 200
#define D_ 128
#define U_ 128
#define G_ 384   // 3*U

typedef unsigned long long ull;

// Scratch (no cudaMalloc allowed)
__device__ float g_xm[(size_t)B_ * T_ * G_];
__device__ int   g_perm[B_];
__device__ __nv_bfloat16 g_whi[G_ * D_];   // [g][k] transposed hi(W)
__device__ __nv_bfloat16 g_wlo[G_ * D_];   // [g][k] transposed lo(W)

// ---------- f32x2 helpers ----------
__device__ __forceinline__ ull pack_dup(float x) {
    ull r; asm("mov.b64 %0, {%1, %1};" : "=l"(r) : "f"(x)); return r;
}
__device__ __forceinline__ ull pack2(float x, float y) {
    ull r; asm("mov.b64 %0, {%1, %2};" : "=l"(r) : "f"(x), "f"(y)); return r;
}
__device__ __forceinline__ void ffma2(ull& d, ull a, ull b) {
    asm("fma.rn.f32x2 %0, %1, %2, %0;" : "+l"(d) : "l"(a), "l"(b));
}
__device__ __forceinline__ ull addf2(ull a, ull b) {
    ull r; asm("add.rn.f32x2 %0, %1, %2;" : "=l"(r) : "l"(a), "l"(b)); return r;
}
__device__ __forceinline__ float2 unpack2(ull v) {
    float2 f; asm("mov.b64 {%0, %1}, %2;" : "=f"(f.x), "=f"(f.y) : "l"(v)); return f;
}
__device__ __forceinline__ float sigm(float x) {
    return __fdividef(1.0f, 1.0f + __expf(-x));
}
__device__ __forceinline__ float tanh_fast(float x) {
    return 1.0f - __fdividef(2.0f, __expf(2.0f * x) + 1.0f);
}

// ---------- tensor helpers ----------
__device__ __forceinline__ void ldsm4(uint32_t& r0, uint32_t& r1, uint32_t& r2, uint32_t& r3, uint32_t addr) {
    asm volatile("ldmatrix.sync.aligned.m8n8.x4.shared.b16 {%0,%1,%2,%3}, [%4];"
                 : "=r"(r0), "=r"(r1), "=r"(r2), "=r"(r3) : "r"(addr));
}
__device__ __forceinline__ void mma16816(float* d, uint32_t a0, uint32_t a1, uint32_t a2, uint32_t a3,
                                         uint32_t b0, uint32_t b1) {
    asm volatile("mma.sync.aligned.m16n8k16.row.col.f32.bf16.bf16.f32 "
                 "{%0,%1,%2,%3},{%4,%5,%6,%7},{%8,%9},{%0,%1,%2,%3};"
                 : "+f"(d[0]), "+f"(d[1]), "+f"(d[2]), "+f"(d[3])
                 : "r"(a0), "r"(a1), "r"(a2), "r"(a3), "r"(b0), "r"(b1));
}
__device__ __forceinline__ uint32_t pack_bf2(__nv_bfloat16 a, __nv_bfloat16 b) {
    uint16_t ua = *(uint16_t*)&a, ub = *(uint16_t*)&b;
    return (uint32_t)ua | ((uint32_t)ub << 16);
}

// ---------- Kernel 0: bitonic sort of batch rows by length (ascending) ----------
__global__ void sort_rows_kernel(const int* __restrict__ slen) {
    __shared__ int key[B_];
    int tid = threadIdx.x;
    key[tid] = slen[tid] * 1024 + tid;
    __syncthreads();
    for (int size = 2; size <= B_; size <<= 1) {
        for (int stride = size >> 1; stride > 0; stride >>= 1) {
            int j = tid ^ stride;
            if (j > tid) {
                int a = key[tid], b = key[j];
                bool up = (tid & size) == 0;
                if ((a > b) == up) { key[tid] = b; key[j] = a; }
            }
            __syncthreads();
        }
    }
    g_perm[tid] = key[tid] & (B_ - 1);
}

// ---------- Kernel 0b: split W into transposed bf16 hi/lo ----------
__global__ void wsplit_kernel(const float* __restrict__ W) {
    int idx = blockIdx.x * 256 + threadIdx.x;   // 49152 = 128*384
    int k = idx / G_, g = idx - k * G_;
    float w = W[(size_t)k * G_ + g];
    __nv_bfloat16 hi = __float2bfloat16(w);
    __nv_bfloat16 lo = __float2bfloat16(w - __bfloat162float(hi));
    g_whi[g * D_ + k] = hi;
    g_wlo[g * D_ + k] = lo;
}

// ---------- Kernel 1: input GEMM via bf16-split-3 tensor cores (unchanged) ----------
__global__ __launch_bounds__(256, 2) void gemm_in_kernel(
    const float* __restrict__ X, const int* __restrict__ slen,
    const float* __restrict__ bias)
{
    int b  = blockIdx.z;
    int t0 = blockIdx.y * 64;
    int n0 = blockIdx.x * 128;
    if (t0 >= slen[b]) return;

    extern __shared__ char smem[];
    __nv_bfloat16* Xhi = (__nv_bfloat16*)smem;   // [64][128]
    __nv_bfloat16* Xlo = Xhi + 64 * 128;         // [64][128]
    __nv_bfloat16* Whi = Xlo + 64 * 128;         // [128][128]
    __nv_bfloat16* Wlo = Whi + 128 * 128;        // [128][128]
    int tid = threadIdx.x;

    const float4* Xg = (const float4*)(X + (size_t)b * T_ * D_);
#pragma unroll
    for (int i = 0; i < 8; i++) {
        int idx = i * 256 + tid;
        int row = idx >> 5, dq = idx & 31;
        int t = t0 + row;
        float4 v = make_float4(0.f, 0.f, 0.f, 0.f);
        if (t < T_) v = Xg[t * 32 + dq];
        __nv_bfloat16 hx = __float2bfloat16(v.x), hy = __float2bfloat16(v.y);
        __nv_bfloat16 hz = __float2bfloat16(v.z), hw = __float2bfloat16(v.w);
        __nv_bfloat16 lx = __float2bfloat16(v.x - __bfloat162float(hx));
        __nv_bfloat16 ly = __float2bfloat16(v.y - __bfloat162float(hy));
        __nv_bfloat16 lz = __float2bfloat16(v.z - __bfloat162float(hz));
        __nv_bfloat16 lw = __float2bfloat16(v.w - __bfloat162float(hw));
        int off = row * 128 + (((dq >> 1) ^ (row & 7)) << 3) + (dq & 1) * 4;
        uint2 hv; hv.x = pack_bf2(hx, hy); hv.y = pack_bf2(hz, hw);
        uint2 lv; lv.x = pack_bf2(lx, ly); lv.y = pack_bf2(lz, lw);
        *(uint2*)(Xhi + off) = hv;
        *(uint2*)(Xlo + off) = lv;
    }
    const uint4* WhiG = (const uint4*)g_whi;
    const uint4* WloG = (const uint4*)g_wlo;
#pragma unroll
    for (int i = 0; i < 8; i++) {
        int idx = i * 256 + tid;
        int n = idx >> 4, c8 = idx & 15;
        int src = (n0 + n) * 16 + c8;
        int dst = n * 16 + (c8 ^ (n & 7));
        ((uint4*)Whi)[dst] = WhiG[src];
        ((uint4*)Wlo)[dst] = WloG[src];
    }
    __syncthreads();

    int lane = tid & 31, wid = tid >> 5;
    int m_off = (wid & 3) * 16;
    int n_off = (wid >> 2) * 64;

    uint32_t XhiB = (uint32_t)__cvta_generic_to_shared(Xhi);
    uint32_t XloB = (uint32_t)__cvta_generic_to_shared(Xlo);
    uint32_t WhiB = (uint32_t)__cvta_generic_to_shared(Whi);
    uint32_t WloB = (uint32_t)__cvta_generic_to_shared(Wlo);

    int ar = m_off + (lane & 15);
    uint32_t arow = ar * 256, axor = (ar & 7), ahi = lane >> 4;
    int brn = n_off + ((lane >> 4) << 3) + (lane & 7);
    uint32_t brow0 = brn * 256, bxor = (brn & 7), bhi = (lane >> 3) & 1;

    float d[8][4];
#pragma unroll
    for (int f = 0; f < 8; f++)
#pragma unroll
        for (int r = 0; r < 4; r++) d[f][r] = 0.f;

#pragma unroll
    for (int ch = 0; ch < 3; ch++) {
        uint32_t Ab = (ch < 2) ? XhiB : XloB;
        uint32_t Bb = (ch == 1) ? WloB : WhiB;
#pragma unroll
        for (int ks = 0; ks < 8; ks++) {
            uint32_t c = ks * 2;
            uint32_t a0, a1, a2, a3;
            ldsm4(a0, a1, a2, a3, Ab + arow + (((c + ahi) ^ axor) << 4));
#pragma unroll
            for (int nb = 0; nb < 4; nb++) {
                uint32_t b0, b1, b2, b3;
                ldsm4(b0, b1, b2, b3, Bb + brow0 + nb * 16 * 256 + (((c + bhi) ^ bxor) << 4));
                mma16816(d[2 * nb],     a0, a1, a2, a3, b0, b1);
                mma16816(d[2 * nb + 1], a0, a1, a2, a3, b2, b3);
            }
        }
    }

    int rloc = m_off + (lane >> 2);
    int trow0 = t0 + rloc, trow1 = trow0 + 8;
    float* o0 = g_xm + ((size_t)b * T_ + trow0) * G_ + n0;
    float* o1 = g_xm + ((size_t)b * T_ + trow1) * G_ + n0;
#pragma unroll
    for (int f = 0; f < 8; f++) {
        int col = n_off + (f >> 1) * 16 + (f & 1) * 8 + (lane & 3) * 2;
        float2 bv = *(const float2*)(bias + n0 + col);
        if (trow0 < T_) *(float2*)(o0 + col) = make_float2(d[f][0] + bv.x, d[f][1] + bv.y);
        if (trow1 < T_) *(float2*)(o1 + col) = make_float2(d[f][2] + bv.x, d[f][3] + bv.y);
    }
}

// ---------- Kernel 2: recurrence, register-R hybrid, 512 threads ----------
// 128 blocks x 512 threads (4 warps/SMSP), 2-pass pairing (group b then 255-b).
// Group g = tid>>7: k in [32g, 32g+32), owns gates of row g.
// Rz,Rr live in REGISTERS (fully-unrolled k loop); Rh in smem; h broadcast as float4.
// Per k per warp LDS: 1 consecutive Rh (1 wf) + 1 broadcast h128 (1 wf).
// Exchange psum layout [slot][group][u] so STS/LDS are consecutive-u (2 wf each).
__global__ __launch_bounds__(512, 1) void recur_kernel(
    const int* __restrict__ slen, const float* __restrict__ R,
    const float* __restrict__ bias, float* __restrict__ out)
{
    extern __shared__ char smraw[];
    float* Rhs  = (float*)smraw;                  // [128k][128u]       65536
    float* hpb  = Rhs + 128 * 128;                // [2][128k][4]        4096
    ull*   psum = (ull*)(hpb + 2 * 128 * 4);      // [6slot][4g][128u]  24576
    __shared__ int rows_s[4], len_s[4];

    int tid = threadIdx.x;
    int u   = tid & 127;
    int g   = tid >> 7;        // 0..3
    int kk0 = g * 32;

    // ---- Rz, Rr into registers (64 coalesced LDGs, fully unrolled) ----
    float rz_[32], rr_[32];
#pragma unroll
    for (int i = 0; i < 32; i++) {
        int k = kk0 + i;
        rz_[i] = R[(size_t)k * G_ + u];
        rr_[i] = R[(size_t)k * G_ + 128 + u];
    }
    // ---- Rh to smem: 4096 float4s / 512 threads = 8 each, coalesced ----
#pragma unroll
    for (int i = 0; i < 8; i++) {
        int f = i * 512 + tid;         // float4 index into [128][32]
        int k = f >> 5, q4 = f & 31;
        float4 v = *(const float4*)(R + (size_t)k * G_ + 256 + q4 * 4);
        *(float4*)(Rhs + k * 128 + q4 * 4) = v;
    }

    ull bz2 = pack_dup(bias[G_ + u]);
    ull br2 = pack_dup(bias[G_ + u + 128]);
    ull bh2 = pack_dup(bias[G_ + u + 256]);

    int zi = g >> 1;       // which pair holds my row
    int lane_sel = g & 1;  // which lane within the pair

    for (int pass = 0; pass < 2; pass++) {
        int gidx = (pass == 0) ? (int)blockIdx.x : (255 - (int)blockIdx.x);

        if (tid < 4) {
            int idx = B_ - 1 - (gidx * 4 + tid);   // descending lengths
            int row = g_perm[idx];
            rows_s[tid] = row;
            len_s[tid]  = slen[row];
        }
        // zero both hp buffers (1024 floats / 512 threads = 2 each)
        hpb[tid] = 0.0f;
        hpb[tid + 512] = 0.0f;
        __syncthreads();

        int maxlen = max(max(len_s[0], len_s[1]), max(len_s[2], len_s[3]));
        int leng = len_s[g];

        const float* xbg = g_xm + (size_t)rows_s[g] * T_ * G_ + u;
        float*       obg = out + (size_t)rows_s[g] * T_ * U_ + u;

        float hg = 0.f, pog = 0.f;
        const float* RhU = Rhs + u;

        for (int t = 0; t < maxlen; t++) {
            // prefetch this row's xm (3 LDGs, hidden behind matvec)
            size_t toff = (size_t)t * G_;
            float xz = xbg[toff], xr = xbg[toff + 128], xh = xbg[toff + 256];

            const float* hpc = hpb + (t & 1) * 512;
            ull z01, z23, r01, r23, q01, q23;
            if (g == 0) { z01 = z23 = bz2; r01 = r23 = br2; q01 = q23 = bh2; }
            else        { z01 = z23 = 0ULL; r01 = r23 = 0ULL; q01 = q23 = 0ULL; }

#pragma unroll
            for (int i = 0; i < 32; i++) {
                int k = kk0 + i;
                ulonglong2 hv = *(const ulonglong2*)(hpc + k * 4);  // (h0,h1),(h2,h3)
                ull rz2 = pack_dup(rz_[i]);
                ull rr2 = pack_dup(rr_[i]);
                ull rh2 = pack_dup(RhU[k * 128]);
                ffma2(z01, hv.x, rz2); ffma2(z23, hv.y, rz2);
                ffma2(r01, hv.x, rr2); ffma2(r23, hv.y, rr2);
                ffma2(q01, hv.x, rh2); ffma2(q23, hv.y, rh2);
            }

            // post all 6 partial pairs; layout [slot][g][u] -> consecutive-u stores
            {
                int base = (g << 7) + u;
                psum[0 * 512 + base] = z01;
                psum[1 * 512 + base] = z23;
                psum[2 * 512 + base] = r01;
                psum[3 * 512 + base] = r23;
                psum[4 * 512 + base] = q01;
                psum[5 * 512 + base] = q23;
            }
            __syncthreads();   // bar1: partials posted; all hp reads done

            {
                ull ez = (zi == 0) ? z01 : z23;
                ull er = (zi == 0) ? r01 : r23;
                ull eq = (zi == 0) ? q01 : q23;
#pragma unroll
                for (int s = 0; s < 4; s++) {
                    if (s == g) continue;
                    int base = (s << 7) + u;
                    ez = addf2(ez, psum[(0 + zi) * 512 + base]);
                    er = addf2(er, psum[(2 + zi) * 512 + base]);
                    eq = addf2(eq, psum[(4 + zi) * 512 + base]);
                }
                float2 az = unpack2(ez), ar2 = unpack2(er), aq = unpack2(eq);
                float azv = lane_sel ? az.y : az.x;
                float arv = lane_sel ? ar2.y : ar2.x;
                float aqv = lane_sel ? aq.y : aq.x;

                float z = sigm(xz + azv), r = sigm(xr + arv);
                float hh = tanh_fast(xh + r * aqv);
                float v = z * hg + (1.0f - z) * hh;
                bool m = t < leng;
                hg = m ? v : hg; pog = m ? v : pog;
                obg[(size_t)t * U_] = pog;

                // publish my row's h into the next hp buffer
                float* hn = hpb + ((t + 1) & 1) * 512;
                hn[u * 4 + g] = hg;
            }
            __syncthreads();   // bar2: new hp published
        }

        // tail: frozen outputs
        for (int t = maxlen; t < T_; t++) {
            obg[(size_t)t * U_] = pog;
        }
        __syncthreads();   // protect rows_s/len_s + hp before next pass
    }
}

extern "C" void kernel_launch(void* const* d_in, const int* in_sizes, int n_in,
                              void* d_out, int out_size)
{
    const float* X    = (const float*)d_in[0];   // [B][T][D]
    const int*   slen = (const int*)d_in[1];     // [B][1]
    const float* W    = (const float*)d_in[2];   // [D][3U]
    const float* R    = (const float*)d_in[3];   // [U][3U]
    const float* bias = (const float*)d_in[4];   // [2][3U]
    float* out = (float*)d_out;                  // [B][T][U]

    (void)in_sizes; (void)n_in; (void)out_size;

    const int gemm_smem  = (64 * 128 * 2 + 128 * 128 * 2) * 2;    // 98304 B
    const int recur_smem = 65536 + 4096 + 24576;                  // 94208 B

    cudaFuncSetAttribute(gemm_in_kernel, cudaFuncAttributeMaxDynamicSharedMemorySize, gemm_smem);
    cudaFuncSetAttribute(recur_kernel,  cudaFuncAttributeMaxDynamicSharedMemorySize, recur_smem);

    sort_rows_kernel<<<1, B_>>>(slen);
    wsplit_kernel<<<192, 256>>>(W);

    dim3 ggrid(3, 4, B_);
    gemm_in_kernel<<<ggrid, 256, gemm_smem>>>(X, slen, bias);

    recur_kernel<<<128, 512, recur_smem>>>(slen, R, bias, out);
}